// round 5
// baseline (speedup 1.0000x reference)
#include <cuda_runtime.h>
#include <cuda_bf16.h>

#define NN   50000
#define NE   800000
#define FIN  128
#define FH   64
#define FOUT 64
#define KC   1024

typedef unsigned long long ull;

// ---------------- scratch (device globals; no allocation) ----------------
__device__ __align__(16) float g_h[NN * FH];      // x @ W1
__device__ __align__(16) float g_agg[NN * FH];    // neighbor aggregation
__device__ __align__(16) float g_x1[NN * FH];     // relu(gcn1)
__device__ __align__(16) float g_deg[NN];
__device__ float g_dinv[NN];
__device__ __align__(16) float g_psum[KC * FH];   // cluster sums
__device__ __align__(16) float g_pcnt[KC];
__device__ __align__(16) float g_A[KC * KC];      // pooled adjacency (0/1)
__device__ __align__(16) float g_degp[KC];
__device__ __align__(16) float g_hps[KC * FH];    // dinv_p[s] * (x_p @ W2)
__device__ __align__(16) float g_xp2[KC * FOUT];  // pooled conv output

// ---------------- helpers ----------------
__device__ __forceinline__ ull pack2(float x, float y) {
    ull r;
    asm("mov.b64 %0, {%1, %2};" : "=l"(r) : "f"(x), "f"(y));
    return r;
}
__device__ __forceinline__ float2 unpack2(ull v) {
    float2 f;
    asm("mov.b64 {%0, %1}, %2;" : "=f"(f.x), "=f"(f.y) : "l"(v));
    return f;
}
__device__ __forceinline__ void ffma2(ull& d, ull a, ull b) {
    asm("fma.rn.f32x2 %0, %1, %2, %0;" : "+l"(d) : "l"(a), "l"(b));
}
__device__ __forceinline__ void red4(float* p, float4 v) {
    asm volatile("red.global.add.v4.f32 [%0], {%1,%2,%3,%4};"
                 :: "l"(p), "f"(v.x), "f"(v.y), "f"(v.z), "f"(v.w) : "memory");
}

// ---------------- small kernels ----------------
__global__ void zero_all_kernel() {
    int i = blockIdx.x * blockDim.x + threadIdx.x;
    float4 z = make_float4(0.f, 0.f, 0.f, 0.f);
    if (i < NN * FH / 4) ((float4*)g_agg)[i] = z;
    if (i < KC * KC / 4) ((float4*)g_A)[i] = z;
    if (i < KC * FH / 4) ((float4*)g_psum)[i] = z;
    if (i < NN / 4)      ((float4*)g_deg)[i] = z;
    if (i < KC / 4) { ((float4*)g_pcnt)[i] = z; ((float4*)g_degp)[i] = z; }
}

// fused: degree atomics + pooled adjacency stores (one edge-list pass)
__global__ void edge_pre_kernel(const int* __restrict__ src, const int* __restrict__ dst,
                                const int* __restrict__ cluster) {
    int e = blockIdx.x * blockDim.x + threadIdx.x;
    if (e < NE) {
        int s = src[e], d = dst[e];
        atomicAdd(&g_deg[d], 1.0f);
        g_A[cluster[s] * KC + cluster[d]] = 1.0f;   // idempotent race
    }
}

__global__ void dinv_kernel() {
    int i = blockIdx.x * blockDim.x + threadIdx.x;
    if (i < NN) g_dinv[i] = rsqrtf(g_deg[i] + 1.0f);
}

// ---------------- gemm1: h = x @ W1  [50000,128]@[128,64] ----------------
// Column-pair f32x2 packing: acc ull = 2 adjacent output cols (1 reg/output).
// Block 128 rows x 64 cols, 256 thr; warp = 32r x 32c; thread = 4r x 8c.
// x read directly from global (L1 broadcast), W1 in smem (row-major = natural
// col-pair ulls). Per 4k: 4 LDG.128 + 8 LDS.128 + 32 MOV(alu) + 64 FFMA2(fma).
__global__ void __launch_bounds__(256, 3) gemm1_kernel(const float* __restrict__ x,
                                                       const float* __restrict__ W1) {
    __shared__ float Ws[FIN * FH];   // 32 KB
    int tid = threadIdx.x;
    for (int i = tid; i < FIN * FH / 4; i += 256)
        ((float4*)Ws)[i] = ((const float4*)W1)[i];
    __syncthreads();

    int lane = tid & 31, warp = tid >> 5;
    int wr = warp >> 1, wc = warp & 1;        // 4 row-bands x 2 col-halves
    int rg = lane >> 2, cg = lane & 3;        // 8 row-groups x 4 col-groups
    int row0 = blockIdx.x * 128 + wr * 32 + rg * 4;
    int col0 = wc * 32 + cg * 8;

    bool rok[4];
    #pragma unroll
    for (int r = 0; r < 4; r++) rok[r] = (row0 + r) < NN;

    ull acc[4][4];
    #pragma unroll
    for (int r = 0; r < 4; r++)
        #pragma unroll
        for (int c = 0; c < 4; c++) acc[r][c] = 0ull;

    #pragma unroll 2
    for (int it = 0; it < FIN / 4; it++) {
        float4 xv[4];
        #pragma unroll
        for (int r = 0; r < 4; r++)
            xv[r] = rok[r] ? ((const float4*)x)[(size_t)(row0 + r) * (FIN / 4) + it]
                           : make_float4(0.f, 0.f, 0.f, 0.f);
        #pragma unroll
        for (int kk = 0; kk < 4; kk++) {
            const ull* wrow = (const ull*)&Ws[(it * 4 + kk) * FH + col0];
            ulonglong2 wA = *(const ulonglong2*)wrow;        // cols c0..c0+3
            ulonglong2 wB = *(const ulonglong2*)(wrow + 2);  // cols c0+4..c0+7
            #pragma unroll
            for (int r = 0; r < 4; r++) {
                const float* xf = (const float*)&xv[r];
                ull xd = pack2(xf[kk], xf[kk]);
                ffma2(acc[r][0], xd, wA.x);
                ffma2(acc[r][1], xd, wA.y);
                ffma2(acc[r][2], xd, wB.x);
                ffma2(acc[r][3], xd, wB.y);
            }
        }
    }

    #pragma unroll
    for (int r = 0; r < 4; r++) {
        if (rok[r]) {
            float2 a = unpack2(acc[r][0]), b = unpack2(acc[r][1]);
            float2 c = unpack2(acc[r][2]), d = unpack2(acc[r][3]);
            float* op = &g_h[(size_t)(row0 + r) * FH + col0];
            *(float4*)op       = make_float4(a.x, a.y, b.x, b.y);
            *(float4*)(op + 4) = make_float4(c.x, c.y, d.x, d.y);
        }
    }
}

// agg[dst] += norm * h[src] ; 16 lanes per edge, float4 per lane, vector red.
__global__ void edge_agg_kernel(const int* __restrict__ src, const int* __restrict__ dst) {
    int tid = blockIdx.x * blockDim.x + threadIdx.x;
    int e = tid >> 4, q = tid & 15;
    if (e >= NE) return;
    int s = src[e], d = dst[e];
    float norm = g_dinv[s] * g_dinv[d];
    float4 h4 = ((const float4*)g_h)[s * 16 + q];
    float4 v = make_float4(h4.x * norm, h4.y * norm, h4.z * norm, h4.w * norm);
    red4(&g_agg[d * FH + q * 4], v);
}

// x1 = relu(agg + dinv^2*h + b1) ; fused cluster-pool scatter.
__global__ void x1_pool_kernel(const int* __restrict__ cluster, const float* __restrict__ b1) {
    int tid = blockIdx.x * blockDim.x + threadIdx.x;
    int n = tid >> 4, q = tid & 15;
    if (n >= NN) return;
    float di = g_dinv[n];
    float selfw = di * di;
    float4 a  = ((const float4*)g_agg)[n * 16 + q];
    float4 h4 = ((const float4*)g_h)[n * 16 + q];
    float4 b  = ((const float4*)b1)[q];
    float4 v;
    v.x = fmaxf(a.x + selfw * h4.x + b.x, 0.f);
    v.y = fmaxf(a.y + selfw * h4.y + b.y, 0.f);
    v.z = fmaxf(a.z + selfw * h4.z + b.z, 0.f);
    v.w = fmaxf(a.w + selfw * h4.w + b.w, 0.f);
    ((float4*)g_x1)[n * 16 + q] = v;
    int c = cluster[n];
    red4(&g_psum[c * FH + q * 4], v);
    if (q == 0) atomicAdd(&g_pcnt[c], 1.0f);
}

__global__ void a_diag_kernel() {
    int t = blockIdx.x * blockDim.x + threadIdx.x;
    if (t < KC) g_A[t * KC + t] = 1.0f;   // A*(1-I)+I => diag exactly 1
}

// deg_p[t] = column sums of A_hat
__global__ void degp_kernel() {
    int t = blockIdx.x * 256 + threadIdx.x;
    int s0 = blockIdx.y * 64;
    float sum = 0.f;
    #pragma unroll 8
    for (int i = 0; i < 64; i++) sum += g_A[(s0 + i) * KC + t];
    atomicAdd(&g_degp[t], sum);
}

// x_p = psum/cnt ; hps = dinv_p[k] * (x_p @ W2)
__global__ void hp_kernel(const float* __restrict__ W2) {
    __shared__ float xp[FH];
    int k = blockIdx.x, f = threadIdx.x;
    float cnt = fmaxf(g_pcnt[k], 1.0f);
    xp[f] = g_psum[k * FH + f] / cnt;
    __syncthreads();
    float acc = 0.f;
    #pragma unroll
    for (int j = 0; j < FH; j++) acc += xp[j] * W2[j * FOUT + f];
    g_hps[k * FH + f] = acc * rsqrtf(g_degp[k]);
}

// x_p2[t,f] = dinv_p[t] * sum_s A_hat[s,t]*hps[s,f] + b2[f]
__global__ void __launch_bounds__(256) xp2_kernel(const float* __restrict__ b2) {
    __shared__ float As[64][8];
    __shared__ float Hs[64][FH];
    int t0 = blockIdx.x * 8;
    int f = threadIdx.x & 63, g = threadIdx.x >> 6;
    float acc[2] = {0.f, 0.f};
    for (int s0 = 0; s0 < KC; s0 += 64) {
        __syncthreads();
        for (int i = threadIdx.x; i < 64 * 8; i += 256) {
            int si = i >> 3, tj = i & 7;
            As[si][tj] = g_A[(s0 + si) * KC + t0 + tj];
        }
        for (int i = threadIdx.x; i < 64 * 64; i += 256)
            Hs[i >> 6][i & 63] = g_hps[(s0 + (i >> 6)) * FH + (i & 63)];
        __syncthreads();
        #pragma unroll 4
        for (int i = 0; i < 64; i++) {
            float hv = Hs[i][f];
            #pragma unroll
            for (int r = 0; r < 2; r++) acc[r] += As[i][g * 2 + r] * hv;
        }
    }
    float bb = b2[f];
    #pragma unroll
    for (int r = 0; r < 2; r++) {
        int t = t0 + g * 2 + r;
        g_xp2[t * FOUT + f] = rsqrtf(g_degp[t]) * acc[r] + bb;
    }
}

// ---------------- final: out = xp2[cluster] + relu(alpha)*(x1@Wskip + bskip) ----
// Same col-pair packed design as gemm1, K=64.
__global__ void __launch_bounds__(256, 3) final_kernel(const int* __restrict__ cluster,
                                                       const float* __restrict__ Wskip,
                                                       const float* __restrict__ bskip,
                                                       const float* __restrict__ alpha,
                                                       float* __restrict__ out) {
    __shared__ float Ws[FH * FOUT];   // 16 KB
    int tid = threadIdx.x;
    for (int i = tid; i < FH * FOUT / 4; i += 256)
        ((float4*)Ws)[i] = ((const float4*)Wskip)[i];
    __syncthreads();

    int lane = tid & 31, warp = tid >> 5;
    int wr = warp >> 1, wc = warp & 1;
    int rg = lane >> 2, cg = lane & 3;
    int row0 = blockIdx.x * 128 + wr * 32 + rg * 4;
    int col0 = wc * 32 + cg * 8;

    float ral = fmaxf(alpha[0], 0.f);
    float4 bb0 = *(const float4*)&bskip[col0];
    float4 bb1 = *(const float4*)&bskip[col0 + 4];

    bool rok[4];
    #pragma unroll
    for (int r = 0; r < 4; r++) rok[r] = (row0 + r) < NN;

    ull acc[4][4];
    #pragma unroll
    for (int r = 0; r < 4; r++)
        #pragma unroll
        for (int c = 0; c < 4; c++) acc[r][c] = 0ull;

    #pragma unroll 2
    for (int it = 0; it < FH / 4; it++) {
        float4 xv[4];
        #pragma unroll
        for (int r = 0; r < 4; r++)
            xv[r] = rok[r] ? ((const float4*)g_x1)[(size_t)(row0 + r) * (FH / 4) + it]
                           : make_float4(0.f, 0.f, 0.f, 0.f);
        #pragma unroll
        for (int kk = 0; kk < 4; kk++) {
            const ull* wrow = (const ull*)&Ws[(it * 4 + kk) * FOUT + col0];
            ulonglong2 wA = *(const ulonglong2*)wrow;
            ulonglong2 wB = *(const ulonglong2*)(wrow + 2);
            #pragma unroll
            for (int r = 0; r < 4; r++) {
                const float* xf = (const float*)&xv[r];
                ull xd = pack2(xf[kk], xf[kk]);
                ffma2(acc[r][0], xd, wA.x);
                ffma2(acc[r][1], xd, wA.y);
                ffma2(acc[r][2], xd, wB.x);
                ffma2(acc[r][3], xd, wB.y);
            }
        }
    }

    #pragma unroll
    for (int r = 0; r < 4; r++) {
        if (rok[r]) {
            int gr = row0 + r;
            int cl = cluster[gr];
            float4 up0 = *(const float4*)&g_xp2[cl * FOUT + col0];
            float4 up1 = *(const float4*)&g_xp2[cl * FOUT + col0 + 4];
            float2 a = unpack2(acc[r][0]), b = unpack2(acc[r][1]);
            float2 c = unpack2(acc[r][2]), d = unpack2(acc[r][3]);
            float4 o0 = make_float4(up0.x + ral * (a.x + bb0.x),
                                    up0.y + ral * (a.y + bb0.y),
                                    up0.z + ral * (b.x + bb0.z),
                                    up0.w + ral * (b.y + bb0.w));
            float4 o1 = make_float4(up1.x + ral * (c.x + bb1.x),
                                    up1.y + ral * (c.y + bb1.y),
                                    up1.z + ral * (d.x + bb1.z),
                                    up1.w + ral * (d.y + bb1.w));
            float* op = &out[(size_t)gr * FOUT + col0];
            *(float4*)op       = o0;
            *(float4*)(op + 4) = o1;
        }
    }
}

// ---------------- launch ----------------
extern "C" void kernel_launch(void* const* d_in, const int* in_sizes, int n_in,
                              void* d_out, int out_size) {
    const float* x       = (const float*)d_in[0];
    const int*   ei      = (const int*)d_in[1];
    const int*   src     = ei;
    const int*   dst     = ei + NE;
    const int*   cluster = (const int*)d_in[2];
    const float* W1      = (const float*)d_in[3];
    const float* b1      = (const float*)d_in[4];
    const float* W2      = (const float*)d_in[5];
    const float* b2      = (const float*)d_in[6];
    const float* Wsk     = (const float*)d_in[7];
    const float* bsk     = (const float*)d_in[8];
    const float* alpha   = (const float*)d_in[9];
    float* out = (float*)d_out;

    const int NB = (NN + 127) / 128;   // 391

    zero_all_kernel<<<(NN * FH / 4 + 255) / 256, 256>>>();
    edge_pre_kernel<<<(NE + 255) / 256, 256>>>(src, dst, cluster);
    dinv_kernel<<<(NN + 255) / 256, 256>>>();
    gemm1_kernel<<<NB, 256>>>(x, W1);
    edge_agg_kernel<<<(NE * 16) / 256, 256>>>(src, dst);
    x1_pool_kernel<<<(NN * 16 + 255) / 256, 256>>>(cluster, b1);
    a_diag_kernel<<<(KC + 255) / 256, 256>>>();
    degp_kernel<<<dim3(4, 16), 256>>>();
    hp_kernel<<<KC, 64>>>(W2);
    xp2_kernel<<<KC / 8, 256>>>(b2);
    final_kernel<<<NB, 256>>>(cluster, Wsk, bsk, alpha, out);
}

// round 6
// speedup vs baseline: 1.4974x; 1.4974x over previous
#include <cuda_runtime.h>
#include <cuda_bf16.h>

#define NN   50000
#define NE   800000
#define FIN  128
#define FH   64
#define FOUT 64
#define KC   1024

typedef unsigned long long ull;

// ---------------- scratch (device globals; no allocation) ----------------
__device__ __align__(16) float g_h[NN * FH];      // h' = dinv * (x @ W1)
__device__ __align__(16) float g_agg[NN * FH];    // sum of h'[src] per dst
__device__ __align__(16) float g_x1[NN * FH];     // relu(gcn1)
__device__ __align__(16) float g_deg[NN];
__device__ float g_dinv[NN];
__device__ __align__(16) float g_psum[KC * FH];   // cluster sums
__device__ __align__(16) float g_pcnt[KC];
__device__ __align__(16) float g_A[KC * KC];      // pooled adjacency (0/1)
__device__ __align__(16) float g_degp[KC];
__device__ __align__(16) float g_hps[KC * FH];    // dinv_p[s] * (x_p @ W2)
__device__ __align__(16) float g_xp2[KC * FOUT];  // pooled conv output

// ---------------- helpers ----------------
__device__ __forceinline__ ull pack2(float x, float y) {
    ull r;
    asm("mov.b64 %0, {%1, %2};" : "=l"(r) : "f"(x), "f"(y));
    return r;
}
__device__ __forceinline__ float2 unpack2(ull v) {
    float2 f;
    asm("mov.b64 {%0, %1}, %2;" : "=f"(f.x), "=f"(f.y) : "l"(v));
    return f;
}
__device__ __forceinline__ void ffma2(ull& d, ull a, ull b) {
    asm("fma.rn.f32x2 %0, %1, %2, %0;" : "+l"(d) : "l"(a), "l"(b));
}
__device__ __forceinline__ void red4(float* p, float4 v) {
    asm volatile("red.global.add.v4.f32 [%0], {%1,%2,%3,%4};"
                 :: "l"(p), "f"(v.x), "f"(v.y), "f"(v.z), "f"(v.w) : "memory");
}

// ---------------- small kernels ----------------
__global__ void zero_all_kernel() {
    int i = blockIdx.x * blockDim.x + threadIdx.x;
    float4 z = make_float4(0.f, 0.f, 0.f, 0.f);
    if (i < NN * FH / 4) ((float4*)g_agg)[i] = z;
    if (i < KC * KC / 4) ((float4*)g_A)[i] = z;
    if (i < KC * FH / 4) ((float4*)g_psum)[i] = z;
    if (i < NN / 4)      ((float4*)g_deg)[i] = z;
    if (i < KC / 4) { ((float4*)g_pcnt)[i] = z; ((float4*)g_degp)[i] = z; }
}

// fused: degree atomics + pooled adjacency stores (one edge-list pass)
__global__ void edge_pre_kernel(const int* __restrict__ src, const int* __restrict__ dst,
                                const int* __restrict__ cluster) {
    int e = blockIdx.x * blockDim.x + threadIdx.x;
    if (e < NE) {
        int s = src[e], d = dst[e];
        atomicAdd(&g_deg[d], 1.0f);
        g_A[cluster[s] * KC + cluster[d]] = 1.0f;   // idempotent race
    }
}

// dinv + pooled-A diagonal (merged)
__global__ void dinv_kernel() {
    int i = blockIdx.x * blockDim.x + threadIdx.x;
    if (i < NN) g_dinv[i] = rsqrtf(g_deg[i] + 1.0f);
    if (i < KC) g_A[i * KC + i] = 1.0f;   // A*(1-I)+I => diag exactly 1
}

// ---------------- gemm1: h' = dinv * (x @ W1)  [50000,128]@[128,64] ----------
// Block 64 rows x 64 cols, 8 warps. Warp = 8 rows x 64 cols (half-warp owns
// 4 rows); thread = 4 rows x 4 cols (acc = 8 ull).
// Per 2-k iter: 2 LDS.128(W) + 4 LDS.64(x) + 8 MOV + 16 FFMA2 -> fma-bound.
#define SXG 132   // xs row stride (floats); 4-row phase diff = 64 mod 128
__global__ void __launch_bounds__(256, 3) gemm1_kernel(const float* __restrict__ x,
                                                       const float* __restrict__ W1) {
    extern __shared__ float smem[];
    float* Ws = smem;                 // [128][64] = 32768 B
    float* xs = smem + FIN * FH;      // [64][SXG] = 33792 B

    int tid = threadIdx.x;
    int row0 = blockIdx.x * 64;

    for (int i = tid; i < FIN * FH / 4; i += 256)
        ((float4*)Ws)[i] = ((const float4*)W1)[i];
    for (int i = tid; i < 64 * 32; i += 256) {
        int r = i >> 5, q = i & 31;
        int gr = row0 + r;
        float4 v = (gr < NN) ? ((const float4*)x)[(size_t)gr * 32 + q]
                             : make_float4(0.f, 0.f, 0.f, 0.f);
        *(float4*)&xs[r * SXG + q * 4] = v;
    }
    __syncthreads();

    int lane = tid & 31, warp = tid >> 5;
    int half = lane >> 4, cq = lane & 15;
    int rbase = warp * 8 + half * 4;     // local rows rbase..rbase+3
    int col0 = cq * 4;

    ull acc[4][2];
    #pragma unroll
    for (int r = 0; r < 4; r++) { acc[r][0] = 0ull; acc[r][1] = 0ull; }

    #pragma unroll 4
    for (int k2 = 0; k2 < FIN / 2; k2++) {
        ulonglong2 w0 = *(const ulonglong2*)&Ws[(2 * k2) * FH + col0];
        ulonglong2 w1 = *(const ulonglong2*)&Ws[(2 * k2 + 1) * FH + col0];
        #pragma unroll
        for (int r = 0; r < 4; r++) {
            float2 xp = *(const float2*)&xs[(rbase + r) * SXG + 2 * k2];
            ull xd0 = pack2(xp.x, xp.x);
            ull xd1 = pack2(xp.y, xp.y);
            ffma2(acc[r][0], xd0, w0.x);
            ffma2(acc[r][1], xd0, w0.y);
            ffma2(acc[r][0], xd1, w1.x);
            ffma2(acc[r][1], xd1, w1.y);
        }
    }

    #pragma unroll
    for (int r = 0; r < 4; r++) {
        int gr = row0 + rbase + r;
        if (gr < NN) {
            float di = g_dinv[gr];
            float2 a = unpack2(acc[r][0]), b = unpack2(acc[r][1]);
            *(float4*)&g_h[(size_t)gr * FH + col0] =
                make_float4(di * a.x, di * a.y, di * b.x, di * b.y);
        }
    }
}

// agg[dst] += h'[src] ; 16 lanes per edge, float4 per lane, vector red.
__global__ void edge_agg_kernel(const int* __restrict__ src, const int* __restrict__ dst) {
    int tid = blockIdx.x * blockDim.x + threadIdx.x;
    int e = tid >> 4, q = tid & 15;
    if (e >= NE) return;
    float4 v = ((const float4*)g_h)[src[e] * 16 + q];
    red4(&g_agg[dst[e] * FH + q * 4], v);
}

// x1 = relu(dinv*(agg + h') + b1) ; fused cluster-pool scatter.
__global__ void x1_pool_kernel(const int* __restrict__ cluster, const float* __restrict__ b1) {
    int tid = blockIdx.x * blockDim.x + threadIdx.x;
    int n = tid >> 4, q = tid & 15;
    if (n >= NN) return;
    float di = g_dinv[n];
    float4 a  = ((const float4*)g_agg)[n * 16 + q];
    float4 h4 = ((const float4*)g_h)[n * 16 + q];
    float4 b  = ((const float4*)b1)[q];
    float4 v;
    v.x = fmaxf(di * (a.x + h4.x) + b.x, 0.f);
    v.y = fmaxf(di * (a.y + h4.y) + b.y, 0.f);
    v.z = fmaxf(di * (a.z + h4.z) + b.z, 0.f);
    v.w = fmaxf(di * (a.w + h4.w) + b.w, 0.f);
    ((float4*)g_x1)[n * 16 + q] = v;
    int c = cluster[n];
    red4(&g_psum[c * FH + q * 4], v);
    if (q == 0) atomicAdd(&g_pcnt[c], 1.0f);
}

// deg_p[t] = column sums of A_hat
__global__ void degp_kernel() {
    int t = blockIdx.x * 256 + threadIdx.x;
    int s0 = blockIdx.y * 64;
    float sum = 0.f;
    #pragma unroll 8
    for (int i = 0; i < 64; i++) sum += g_A[(s0 + i) * KC + t];
    atomicAdd(&g_degp[t], sum);
}

// x_p = psum/cnt ; hps = dinv_p[k] * (x_p @ W2)
__global__ void hp_kernel(const float* __restrict__ W2) {
    __shared__ float xp[FH];
    int k = blockIdx.x, f = threadIdx.x;
    float cnt = fmaxf(g_pcnt[k], 1.0f);
    xp[f] = g_psum[k * FH + f] / cnt;
    __syncthreads();
    float acc = 0.f;
    #pragma unroll
    for (int j = 0; j < FH; j++) acc += xp[j] * W2[j * FOUT + f];
    g_hps[k * FH + f] = acc * rsqrtf(g_degp[k]);
}

// x_p2[t,f] = dinv_p[t] * sum_s A_hat[s,t]*hps[s,f] + b2[f]
__global__ void __launch_bounds__(256) xp2_kernel(const float* __restrict__ b2) {
    __shared__ float As[64][8];
    __shared__ float Hs[64][FH];
    int t0 = blockIdx.x * 8;
    int f = threadIdx.x & 63, g = threadIdx.x >> 6;
    float acc[2] = {0.f, 0.f};
    for (int s0 = 0; s0 < KC; s0 += 64) {
        __syncthreads();
        for (int i = threadIdx.x; i < 64 * 8; i += 256) {
            int si = i >> 3, tj = i & 7;
            As[si][tj] = g_A[(s0 + si) * KC + t0 + tj];
        }
        for (int i = threadIdx.x; i < 64 * 64; i += 256)
            Hs[i >> 6][i & 63] = g_hps[(s0 + (i >> 6)) * FH + (i & 63)];
        __syncthreads();
        #pragma unroll 4
        for (int i = 0; i < 64; i++) {
            float hv = Hs[i][f];
            #pragma unroll
            for (int r = 0; r < 2; r++) acc[r] += As[i][g * 2 + r] * hv;
        }
    }
    float bb = b2[f];
    #pragma unroll
    for (int r = 0; r < 2; r++) {
        int t = t0 + g * 2 + r;
        g_xp2[t * FOUT + f] = rsqrtf(g_degp[t]) * acc[r] + bb;
    }
}

// ---------------- final: out = xp2[cluster] + relu(alpha)*(x1@Wskip + bskip) ----
// Same geometry as gemm1, K=64.
#define SXF 68    // xs row stride (floats); 4-row phase diff = 64 mod 128
__global__ void __launch_bounds__(256, 4) final_kernel(const int* __restrict__ cluster,
                                                       const float* __restrict__ Wskip,
                                                       const float* __restrict__ bskip,
                                                       const float* __restrict__ alpha,
                                                       float* __restrict__ out) {
    extern __shared__ float smem[];
    float* Ws = smem;                // [64][64] = 16384 B
    float* xs = smem + FH * FOUT;    // [64][SXF] = 17408 B

    int tid = threadIdx.x;
    int row0 = blockIdx.x * 64;

    for (int i = tid; i < FH * FOUT / 4; i += 256)
        ((float4*)Ws)[i] = ((const float4*)Wskip)[i];
    for (int i = tid; i < 64 * 16; i += 256) {
        int r = i >> 4, q = i & 15;
        int gr = row0 + r;
        float4 v = (gr < NN) ? ((const float4*)g_x1)[(size_t)gr * 16 + q]
                             : make_float4(0.f, 0.f, 0.f, 0.f);
        *(float4*)&xs[r * SXF + q * 4] = v;
    }
    __syncthreads();

    int lane = tid & 31, warp = tid >> 5;
    int half = lane >> 4, cq = lane & 15;
    int rbase = warp * 8 + half * 4;
    int col0 = cq * 4;

    float ral = fmaxf(alpha[0], 0.f);
    float4 bb = *(const float4*)&bskip[col0];

    ull acc[4][2];
    #pragma unroll
    for (int r = 0; r < 4; r++) { acc[r][0] = 0ull; acc[r][1] = 0ull; }

    #pragma unroll 4
    for (int k2 = 0; k2 < FH / 2; k2++) {
        ulonglong2 w0 = *(const ulonglong2*)&Ws[(2 * k2) * FOUT + col0];
        ulonglong2 w1 = *(const ulonglong2*)&Ws[(2 * k2 + 1) * FOUT + col0];
        #pragma unroll
        for (int r = 0; r < 4; r++) {
            float2 xp = *(const float2*)&xs[(rbase + r) * SXF + 2 * k2];
            ull xd0 = pack2(xp.x, xp.x);
            ull xd1 = pack2(xp.y, xp.y);
            ffma2(acc[r][0], xd0, w0.x);
            ffma2(acc[r][1], xd0, w0.y);
            ffma2(acc[r][0], xd1, w1.x);
            ffma2(acc[r][1], xd1, w1.y);
        }
    }

    #pragma unroll
    for (int r = 0; r < 4; r++) {
        int gr = row0 + rbase + r;
        if (gr < NN) {
            int cl = cluster[gr];
            float4 up = *(const float4*)&g_xp2[cl * FOUT + col0];
            float2 a = unpack2(acc[r][0]), b = unpack2(acc[r][1]);
            float4 o = make_float4(up.x + ral * (a.x + bb.x),
                                   up.y + ral * (a.y + bb.y),
                                   up.z + ral * (b.x + bb.z),
                                   up.w + ral * (b.y + bb.w));
            *(float4*)&out[(size_t)gr * FOUT + col0] = o;
        }
    }
}

// ---------------- launch ----------------
extern "C" void kernel_launch(void* const* d_in, const int* in_sizes, int n_in,
                              void* d_out, int out_size) {
    const float* x       = (const float*)d_in[0];
    const int*   ei      = (const int*)d_in[1];
    const int*   src     = ei;
    const int*   dst     = ei + NE;
    const int*   cluster = (const int*)d_in[2];
    const float* W1      = (const float*)d_in[3];
    const float* b1      = (const float*)d_in[4];
    const float* W2      = (const float*)d_in[5];
    const float* b2      = (const float*)d_in[6];
    const float* Wsk     = (const float*)d_in[7];
    const float* bsk     = (const float*)d_in[8];
    const float* alpha   = (const float*)d_in[9];
    float* out = (float*)d_out;

    const int SMEM1 = (FIN * FH + 64 * SXG) * 4;   // 32768 + 33792 = 66560 B
    const int SMEM2 = (FH * FOUT + 64 * SXF) * 4;  // 16384 + 17408 = 33792 B
    cudaFuncSetAttribute(gemm1_kernel, cudaFuncAttributeMaxDynamicSharedMemorySize, SMEM1);
    cudaFuncSetAttribute(final_kernel, cudaFuncAttributeMaxDynamicSharedMemorySize, SMEM2);

    const int NB = (NN + 63) / 64;   // 782

    zero_all_kernel<<<(NN * FH / 4 + 255) / 256, 256>>>();
    edge_pre_kernel<<<(NE + 255) / 256, 256>>>(src, dst, cluster);
    dinv_kernel<<<(NN + 255) / 256, 256>>>();
    gemm1_kernel<<<NB, 256, SMEM1>>>(x, W1);
    edge_agg_kernel<<<(NE * 16) / 256, 256>>>(src, dst);
    x1_pool_kernel<<<(NN * 16 + 255) / 256, 256>>>(cluster, b1);
    degp_kernel<<<dim3(4, 16), 256>>>();
    hp_kernel<<<KC, 64>>>(W2);
    xp2_kernel<<<KC / 8, 256>>>(b2);
    final_kernel<<<NB, 256, SMEM2>>>(cluster, Wsk, bsk, alpha, out);
}

// round 13
// speedup vs baseline: 1.7108x; 1.1425x over previous
#include <cuda_runtime.h>
#include <cuda_bf16.h>

#define NN   50000
#define NE   800000
#define FIN  128
#define FH   64
#define FOUT 64
#define KC   1024

typedef unsigned long long ull;

// ---------------- scratch (device globals; no allocation) ----------------
__device__ __align__(16) float g_h[NN * FH];      // h' = dinv * (x @ W1)
__device__ __align__(16) float g_x1[NN * FH];     // relu(gcn1)
__device__ __align__(16) int   g_degi[NN];        // in-degree (int)
__device__ float g_dinv[NN];
__device__ __align__(16) int   g_ptr[NN];         // CSR row starts
__device__ __align__(16) int   g_cursor[NN];      // scatter cursors
__device__ __align__(16) int   g_csrc[NE];        // CSR src indices (by dst)
__device__ int g_bsum[256];
__device__ int g_bofs[256];
__device__ __align__(16) float g_psum[KC * FH];   // cluster sums
__device__ __align__(16) float g_pcnt[KC];
__device__ __align__(16) float g_A[KC * KC];      // pooled adjacency (0/1)
__device__ __align__(16) float g_degp[KC];
__device__ __align__(16) float g_hps[KC * FH];    // dinv_p[s] * (x_p @ W2)
__device__ __align__(16) float g_xp2[KC * FOUT];  // pooled conv output

// ---------------- helpers ----------------
__device__ __forceinline__ ull pack2(float x, float y) {
    ull r;
    asm("mov.b64 %0, {%1, %2};" : "=l"(r) : "f"(x), "f"(y));
    return r;
}
__device__ __forceinline__ float2 unpack2(ull v) {
    float2 f;
    asm("mov.b64 {%0, %1}, %2;" : "=f"(f.x), "=f"(f.y) : "l"(v));
    return f;
}
__device__ __forceinline__ void ffma2(ull& d, ull a, ull b) {
    asm("fma.rn.f32x2 %0, %1, %2, %0;" : "+l"(d) : "l"(a), "l"(b));
}
__device__ __forceinline__ void red2(float* p, float2 v) {
    asm volatile("red.global.add.v2.f32 [%0], {%1,%2};"
                 :: "l"(p), "f"(v.x), "f"(v.y) : "memory");
}

// ---------------- setup kernels ----------------
__global__ void zero_all_kernel() {
    int i = blockIdx.x * blockDim.x + threadIdx.x;   // 262144 threads
    float4 z = make_float4(0.f, 0.f, 0.f, 0.f);
    if (i < KC * KC / 4) ((float4*)g_A)[i] = z;
    if (i < KC * FH / 4) ((float4*)g_psum)[i] = z;
    if (i < NN / 4)      ((int4*)g_degi)[i] = make_int4(0, 0, 0, 0);
    if (i < KC / 4) { ((float4*)g_pcnt)[i] = z; ((float4*)g_degp)[i] = z; }
}

// degree counts + pooled adjacency stores (one edge-list pass)
__global__ void edge_pre_kernel(const int* __restrict__ src, const int* __restrict__ dst,
                                const int* __restrict__ cluster) {
    int e = blockIdx.x * blockDim.x + threadIdx.x;
    if (e < NE) {
        int s = src[e], d = dst[e];
        atomicAdd(&g_degi[d], 1);
        g_A[cluster[s] * KC + cluster[d]] = 1.0f;   // idempotent race
    }
}

// per-block degree sums (196 blocks x 256)
__global__ void blocksum_kernel() {
    __shared__ int sh[256];
    int i = blockIdx.x * 256 + threadIdx.x;
    sh[threadIdx.x] = (i < NN) ? g_degi[i] : 0;
    __syncthreads();
    for (int s = 128; s > 0; s >>= 1) {
        if (threadIdx.x < s) sh[threadIdx.x] += sh[threadIdx.x + s];
        __syncthreads();
    }
    if (threadIdx.x == 0) g_bsum[blockIdx.x] = sh[0];
}

// exclusive scan of the 196 block sums (1 block)
__global__ void scan_offsets_kernel() {
    __shared__ int sh[256];
    int t = threadIdx.x;
    const int nb = (NN + 255) / 256;   // 196
    int v = (t < nb) ? g_bsum[t] : 0;
    sh[t] = v;
    __syncthreads();
    for (int d = 1; d < 256; d <<= 1) {
        int add = (t >= d) ? sh[t - d] : 0;
        __syncthreads();
        sh[t] += add;
        __syncthreads();
    }
    if (t < nb) g_bofs[t] = sh[t] - v;
}

// per-node exclusive offsets + cursors + dinv + pooled-A diagonal
__global__ void fill_ptr_kernel() {
    __shared__ int wsum[8];
    __shared__ int wpre[8];
    int i = blockIdx.x * 256 + threadIdx.x;
    int lane = threadIdx.x & 31, w = threadIdx.x >> 5;
    int v = (i < NN) ? g_degi[i] : 0;
    int x = v;
    #pragma unroll
    for (int d = 1; d < 32; d <<= 1) {
        int y = __shfl_up_sync(0xffffffffu, x, d);
        if (lane >= d) x += y;
    }
    if (lane == 31) wsum[w] = x;
    __syncthreads();
    if (threadIdx.x == 0) {
        int s = 0;
        #pragma unroll
        for (int j = 0; j < 8; j++) { wpre[j] = s; s += wsum[j]; }
    }
    __syncthreads();
    int excl = g_bofs[blockIdx.x] + wpre[w] + x - v;
    if (i < NN) {
        g_ptr[i] = excl;
        g_cursor[i] = excl;
        g_dinv[i] = rsqrtf((float)v + 1.0f);
    }
    if (i < KC) g_A[i * KC + i] = 1.0f;   // A*(1-I)+I => diag exactly 1
}

// bucket edges by dst
__global__ void scatter_kernel(const int* __restrict__ src, const int* __restrict__ dst) {
    int e = blockIdx.x * blockDim.x + threadIdx.x;
    if (e < NE) {
        int pos = atomicAdd(&g_cursor[dst[e]], 1);
        g_csrc[pos] = src[e];
    }
}

// ---------------- gemm1: h' = dinv * (x @ W1)  (proven R5 SIMT) ------------
#define SXG 132
__global__ void __launch_bounds__(256, 3) gemm1_kernel(const float* __restrict__ x,
                                                       const float* __restrict__ W1) {
    extern __shared__ float smem[];
    float* Ws = smem;                 // [128][64]
    float* xs = smem + FIN * FH;      // [64][SXG]

    int tid = threadIdx.x;
    int row0 = blockIdx.x * 64;

    for (int i = tid; i < FIN * FH / 4; i += 256)
        ((float4*)Ws)[i] = ((const float4*)W1)[i];
    for (int i = tid; i < 64 * 32; i += 256) {
        int r = i >> 5, q = i & 31;
        int gr = row0 + r;
        float4 v = (gr < NN) ? ((const float4*)x)[(size_t)gr * 32 + q]
                             : make_float4(0.f, 0.f, 0.f, 0.f);
        *(float4*)&xs[r * SXG + q * 4] = v;
    }
    __syncthreads();

    int lane = tid & 31, warp = tid >> 5;
    int half = lane >> 4, cq = lane & 15;
    int rbase = warp * 8 + half * 4;
    int col0 = cq * 4;

    ull acc[4][2];
    #pragma unroll
    for (int r = 0; r < 4; r++) { acc[r][0] = 0ull; acc[r][1] = 0ull; }

    #pragma unroll 4
    for (int k2 = 0; k2 < FIN / 2; k2++) {
        ulonglong2 w0 = *(const ulonglong2*)&Ws[(2 * k2) * FH + col0];
        ulonglong2 w1 = *(const ulonglong2*)&Ws[(2 * k2 + 1) * FH + col0];
        #pragma unroll
        for (int r = 0; r < 4; r++) {
            float2 xp = *(const float2*)&xs[(rbase + r) * SXG + 2 * k2];
            ull xd0 = pack2(xp.x, xp.x);
            ull xd1 = pack2(xp.y, xp.y);
            ffma2(acc[r][0], xd0, w0.x);
            ffma2(acc[r][1], xd0, w0.y);
            ffma2(acc[r][0], xd1, w1.x);
            ffma2(acc[r][1], xd1, w1.y);
        }
    }

    #pragma unroll
    for (int r = 0; r < 4; r++) {
        int gr = row0 + rbase + r;
        if (gr < NN) {
            float di = g_dinv[gr];
            float2 a = unpack2(acc[r][0]), b = unpack2(acc[r][1]);
            *(float4*)&g_h[(size_t)gr * FH + col0] =
                make_float4(di * a.x, di * a.y, di * b.x, di * b.y);
        }
    }
}

// ---------------- fused CSR aggregate + x1 + cluster pool ------------------
// Warp per node: acc = sum h'[neighbors]; x1 = relu(dinv*(acc+h'n)+b1);
// store x1 + scatter into psum/pcnt. Lane owns 2 feature cols.
__global__ void __launch_bounds__(256) node_agg_kernel(const int* __restrict__ cluster,
                                                       const float* __restrict__ b1) {
    int n = (blockIdx.x * 256 + threadIdx.x) >> 5;
    int lane = threadIdx.x & 31;
    if (n >= NN) return;
    int beg = g_ptr[n], dg = g_degi[n];
    int end = beg + dg;
    float2 acc = make_float2(0.f, 0.f);
    int j = beg;
    for (; j + 4 <= end; j += 4) {
        int s0 = g_csrc[j], s1 = g_csrc[j + 1], s2 = g_csrc[j + 2], s3 = g_csrc[j + 3];
        float2 h0 = ((const float2*)g_h)[s0 * 32 + lane];
        float2 h1 = ((const float2*)g_h)[s1 * 32 + lane];
        float2 h2 = ((const float2*)g_h)[s2 * 32 + lane];
        float2 h3 = ((const float2*)g_h)[s3 * 32 + lane];
        acc.x += (h0.x + h1.x) + (h2.x + h3.x);
        acc.y += (h0.y + h1.y) + (h2.y + h3.y);
    }
    for (; j < end; j++) {
        int s = g_csrc[j];
        float2 hv = ((const float2*)g_h)[s * 32 + lane];
        acc.x += hv.x; acc.y += hv.y;
    }
    float2 hn = ((const float2*)g_h)[n * 32 + lane];
    float di = g_dinv[n];
    float2 b = ((const float2*)b1)[lane];
    float2 v;
    v.x = fmaxf(di * (acc.x + hn.x) + b.x, 0.f);
    v.y = fmaxf(di * (acc.y + hn.y) + b.y, 0.f);
    ((float2*)g_x1)[n * 32 + lane] = v;
    int c = cluster[n];
    red2(&g_psum[c * FH + lane * 2], v);
    if (lane == 0) atomicAdd(&g_pcnt[c], 1.0f);
}

// deg_p[t] = column sums of A_hat
__global__ void degp_kernel() {
    int t = blockIdx.x * 256 + threadIdx.x;
    int s0 = blockIdx.y * 64;
    float sum = 0.f;
    #pragma unroll 8
    for (int i = 0; i < 64; i++) sum += g_A[(s0 + i) * KC + t];
    atomicAdd(&g_degp[t], sum);
}

// x_p = psum/cnt ; hps = dinv_p[k] * (x_p @ W2)
__global__ void hp_kernel(const float* __restrict__ W2) {
    __shared__ float xp[FH];
    int k = blockIdx.x, f = threadIdx.x;
    float cnt = fmaxf(g_pcnt[k], 1.0f);
    xp[f] = g_psum[k * FH + f] / cnt;
    __syncthreads();
    float acc = 0.f;
    #pragma unroll
    for (int j = 0; j < FH; j++) acc += xp[j] * W2[j * FOUT + f];
    g_hps[k * FH + f] = acc * rsqrtf(g_degp[k]);
}

// x_p2[t,f] = dinv_p[t] * sum_s A_hat[s,t]*hps[s,f] + b2[f]
__global__ void __launch_bounds__(256) xp2_kernel(const float* __restrict__ b2) {
    __shared__ float As[64][8];
    __shared__ float Hs[64][FH];
    int t0 = blockIdx.x * 8;
    int f = threadIdx.x & 63, g = threadIdx.x >> 6;
    float acc[2] = {0.f, 0.f};
    for (int s0 = 0; s0 < KC; s0 += 64) {
        __syncthreads();
        for (int i = threadIdx.x; i < 64 * 8; i += 256) {
            int si = i >> 3, tj = i & 7;
            As[si][tj] = g_A[(s0 + si) * KC + t0 + tj];
        }
        for (int i = threadIdx.x; i < 64 * 64; i += 256)
            Hs[i >> 6][i & 63] = g_hps[(s0 + (i >> 6)) * FH + (i & 63)];
        __syncthreads();
        #pragma unroll 4
        for (int i = 0; i < 64; i++) {
            float hv = Hs[i][f];
            #pragma unroll
            for (int r = 0; r < 2; r++) acc[r] += As[i][g * 2 + r] * hv;
        }
    }
    float bb = b2[f];
    #pragma unroll
    for (int r = 0; r < 2; r++) {
        int t = t0 + g * 2 + r;
        g_xp2[t * FOUT + f] = rsqrtf(g_degp[t]) * acc[r] + bb;
    }
}

// ---------------- final: out = xp2[cluster] + relu(alpha)*(x1@Wskip + bskip) ----
#define SXF 68
__global__ void __launch_bounds__(256, 4) final_kernel(const int* __restrict__ cluster,
                                                       const float* __restrict__ Wskip,
                                                       const float* __restrict__ bskip,
                                                       const float* __restrict__ alpha,
                                                       float* __restrict__ out) {
    extern __shared__ float fsmem[];
    float* Ws = fsmem;
    float* xs = fsmem + FH * FOUT;

    int tid = threadIdx.x;
    int row0 = blockIdx.x * 64;

    for (int i = tid; i < FH * FOUT / 4; i += 256)
        ((float4*)Ws)[i] = ((const float4*)Wskip)[i];
    for (int i = tid; i < 64 * 16; i += 256) {
        int r = i >> 4, q = i & 15;
        int gr = row0 + r;
        float4 v = (gr < NN) ? ((const float4*)g_x1)[(size_t)gr * 16 + q]
                             : make_float4(0.f, 0.f, 0.f, 0.f);
        *(float4*)&xs[r * SXF + q * 4] = v;
    }
    __syncthreads();

    int lane = tid & 31, warp = tid >> 5;
    int half = lane >> 4, cq = lane & 15;
    int rbase = warp * 8 + half * 4;
    int col0 = cq * 4;

    float ral = fmaxf(alpha[0], 0.f);
    float4 bb = *(const float4*)&bskip[col0];

    ull acc[4][2];
    #pragma unroll
    for (int r = 0; r < 4; r++) { acc[r][0] = 0ull; acc[r][1] = 0ull; }

    #pragma unroll 4
    for (int k2 = 0; k2 < FH / 2; k2++) {
        ulonglong2 w0 = *(const ulonglong2*)&Ws[(2 * k2) * FOUT + col0];
        ulonglong2 w1 = *(const ulonglong2*)&Ws[(2 * k2 + 1) * FOUT + col0];
        #pragma unroll
        for (int r = 0; r < 4; r++) {
            float2 xp = *(const float2*)&xs[(rbase + r) * SXF + 2 * k2];
            ull xd0 = pack2(xp.x, xp.x);
            ull xd1 = pack2(xp.y, xp.y);
            ffma2(acc[r][0], xd0, w0.x);
            ffma2(acc[r][1], xd0, w0.y);
            ffma2(acc[r][0], xd1, w1.x);
            ffma2(acc[r][1], xd1, w1.y);
        }
    }

    #pragma unroll
    for (int r = 0; r < 4; r++) {
        int gr = row0 + rbase + r;
        if (gr < NN) {
            int cl = cluster[gr];
            float4 up = *(const float4*)&g_xp2[cl * FOUT + col0];
            float2 a = unpack2(acc[r][0]), b = unpack2(acc[r][1]);
            float4 o = make_float4(up.x + ral * (a.x + bb.x),
                                   up.y + ral * (a.y + bb.y),
                                   up.z + ral * (b.x + bb.z),
                                   up.w + ral * (b.y + bb.w));
            *(float4*)&out[(size_t)gr * FOUT + col0] = o;
        }
    }
}

// ---------------- launch ----------------
extern "C" void kernel_launch(void* const* d_in, const int* in_sizes, int n_in,
                              void* d_out, int out_size) {
    const float* x       = (const float*)d_in[0];
    const int*   ei      = (const int*)d_in[1];
    const int*   src     = ei;
    const int*   dst     = ei + NE;
    const int*   cluster = (const int*)d_in[2];
    const float* W1      = (const float*)d_in[3];
    const float* b1      = (const float*)d_in[4];
    const float* W2      = (const float*)d_in[5];
    const float* b2      = (const float*)d_in[6];
    const float* Wsk     = (const float*)d_in[7];
    const float* bsk     = (const float*)d_in[8];
    const float* alpha   = (const float*)d_in[9];
    float* out = (float*)d_out;

    const int SMEM1 = (FIN * FH + 64 * SXG) * 4;   // 66560 B
    const int SMEM2 = (FH * FOUT + 64 * SXF) * 4;  // 33792 B
    cudaFuncSetAttribute(gemm1_kernel, cudaFuncAttributeMaxDynamicSharedMemorySize, SMEM1);
    cudaFuncSetAttribute(final_kernel, cudaFuncAttributeMaxDynamicSharedMemorySize, SMEM2);

    const int NBN = (NN + 255) / 256;   // 196

    zero_all_kernel<<<(KC * KC / 4 + 255) / 256, 256>>>();
    edge_pre_kernel<<<(NE + 255) / 256, 256>>>(src, dst, cluster);
    blocksum_kernel<<<NBN, 256>>>();
    scan_offsets_kernel<<<1, 256>>>();
    fill_ptr_kernel<<<NBN, 256>>>();
    gemm1_kernel<<<(NN + 63) / 64, 256, SMEM1>>>(x, W1);
    scatter_kernel<<<(NE + 255) / 256, 256>>>(src, dst);
    node_agg_kernel<<<(NN * 32 + 255) / 256, 256>>>(cluster, b1);
    degp_kernel<<<dim3(4, 16), 256>>>();
    hp_kernel<<<KC, 64>>>(W2);
    xp2_kernel<<<KC / 8, 256>>>(b2);
    final_kernel<<<(NN + 63) / 64, 256, SMEM2>>>(cluster, Wsk, bsk, alpha, out);
}

// round 15
// speedup vs baseline: 1.7300x; 1.0112x over previous
#include <cuda_runtime.h>
#include <cuda_bf16.h>

#define NN   50000
#define NE   800000
#define FIN  128
#define FH   64
#define FOUT 64
#define KC   1024

typedef unsigned long long ull;

// ---------------- scratch (device globals; no allocation) ----------------
__device__ __align__(16) float g_h[NN * FH];      // h' = dinv * (x @ W1)
__device__ __align__(16) float g_x1[NN * FH];     // relu(gcn1)
__device__ __align__(16) int   g_degi[NN];        // in-degree (int)
__device__ float g_dinv[NN];
__device__ __align__(16) int   g_ptr[NN];         // CSR row starts
__device__ __align__(16) int   g_cursor[NN];      // scatter cursors
__device__ __align__(16) int   g_csrc[NE];        // CSR src indices (by dst)
__device__ int g_total;                           // CSR bump allocator
__device__ __align__(16) float g_psum[KC * FH];   // cluster sums
__device__ __align__(16) float g_pcnt[KC];
__device__ __align__(16) float g_A[KC * KC];      // pooled adjacency (0/1)
__device__ __align__(16) float g_degp[KC];
__device__ __align__(16) float g_hps[KC * FH];    // dinv_p[s] * (x_p @ W2)
__device__ __align__(16) float g_xp2[KC * FOUT];  // pooled conv output

// ---------------- helpers ----------------
__device__ __forceinline__ ull pack2(float x, float y) {
    ull r;
    asm("mov.b64 %0, {%1, %2};" : "=l"(r) : "f"(x), "f"(y));
    return r;
}
__device__ __forceinline__ float2 unpack2(ull v) {
    float2 f;
    asm("mov.b64 {%0, %1}, %2;" : "=f"(f.x), "=f"(f.y) : "l"(v));
    return f;
}
__device__ __forceinline__ void ffma2(ull& d, ull a, ull b) {
    asm("fma.rn.f32x2 %0, %1, %2, %0;" : "+l"(d) : "l"(a), "l"(b));
}
__device__ __forceinline__ void red2(float* p, float2 v) {
    asm volatile("red.global.add.v2.f32 [%0], {%1,%2};"
                 :: "l"(p), "f"(v.x), "f"(v.y) : "memory");
}

// ---------------- setup kernels ----------------
__global__ void zero_all_kernel() {
    int i = blockIdx.x * blockDim.x + threadIdx.x;
    float4 z = make_float4(0.f, 0.f, 0.f, 0.f);
    if (i < KC * KC / 4) ((float4*)g_A)[i] = z;
    if (i < KC * FH / 4) ((float4*)g_psum)[i] = z;
    if (i < NN / 4)      ((int4*)g_degi)[i] = make_int4(0, 0, 0, 0);
    if (i < KC / 4) { ((float4*)g_pcnt)[i] = z; ((float4*)g_degp)[i] = z; }
    if (i == 0) g_total = 0;
}

// degree counts + pooled adjacency stores (one edge-list pass)
__global__ void edge_pre_kernel(const int* __restrict__ src, const int* __restrict__ dst,
                                const int* __restrict__ cluster) {
    int e = blockIdx.x * blockDim.x + threadIdx.x;
    if (e < NE) {
        int s = src[e], d = dst[e];
        atomicAdd(&g_degi[d], 1);
        g_A[cluster[s] * KC + cluster[d]] = 1.0f;   // idempotent race
    }
}

// CSR offsets in ONE kernel: block scan + atomic bump allocator for the block
// base. Region assignment is arrival-order dependent (disjoint + contiguous
// regardless) — affects only fp summand order downstream.
__global__ void ptr_kernel() {
    __shared__ int wsum[8];
    __shared__ int wpre[8];
    __shared__ int sbase;
    int i = blockIdx.x * 256 + threadIdx.x;
    int lane = threadIdx.x & 31, w = threadIdx.x >> 5;
    int v = (i < NN) ? g_degi[i] : 0;
    int x = v;
    #pragma unroll
    for (int d = 1; d < 32; d <<= 1) {
        int y = __shfl_up_sync(0xffffffffu, x, d);
        if (lane >= d) x += y;
    }
    if (lane == 31) wsum[w] = x;
    __syncthreads();
    if (threadIdx.x == 0) {
        int s = 0;
        #pragma unroll
        for (int j = 0; j < 8; j++) { wpre[j] = s; s += wsum[j]; }
        sbase = atomicAdd(&g_total, s);
    }
    __syncthreads();
    int excl = sbase + wpre[w] + x - v;
    if (i < NN) {
        g_ptr[i] = excl;
        g_cursor[i] = excl;
        g_dinv[i] = rsqrtf((float)v + 1.0f);
    }
    if (i < KC) g_A[i * KC + i] = 1.0f;   // A*(1-I)+I => diag exactly 1
}

// bucket edges by dst
__global__ void scatter_kernel(const int* __restrict__ src, const int* __restrict__ dst) {
    int e = blockIdx.x * blockDim.x + threadIdx.x;
    if (e < NE) {
        int pos = atomicAdd(&g_cursor[dst[e]], 1);
        g_csrc[pos] = src[e];
    }
}

// ---------------- gemm1: h' = dinv * (x @ W1)  (proven R5 SIMT) ------------
#define SXG 132
__global__ void __launch_bounds__(256, 3) gemm1_kernel(const float* __restrict__ x,
                                                       const float* __restrict__ W1) {
    extern __shared__ float smem[];
    float* Ws = smem;                 // [128][64]
    float* xs = smem + FIN * FH;      // [64][SXG]

    int tid = threadIdx.x;
    int row0 = blockIdx.x * 64;

    for (int i = tid; i < FIN * FH / 4; i += 256)
        ((float4*)Ws)[i] = ((const float4*)W1)[i];
    for (int i = tid; i < 64 * 32; i += 256) {
        int r = i >> 5, q = i & 31;
        int gr = row0 + r;
        float4 v = (gr < NN) ? ((const float4*)x)[(size_t)gr * 32 + q]
                             : make_float4(0.f, 0.f, 0.f, 0.f);
        *(float4*)&xs[r * SXG + q * 4] = v;
    }
    __syncthreads();

    int lane = tid & 31, warp = tid >> 5;
    int half = lane >> 4, cq = lane & 15;
    int rbase = warp * 8 + half * 4;
    int col0 = cq * 4;

    ull acc[4][2];
    #pragma unroll
    for (int r = 0; r < 4; r++) { acc[r][0] = 0ull; acc[r][1] = 0ull; }

    #pragma unroll 4
    for (int k2 = 0; k2 < FIN / 2; k2++) {
        ulonglong2 w0 = *(const ulonglong2*)&Ws[(2 * k2) * FH + col0];
        ulonglong2 w1 = *(const ulonglong2*)&Ws[(2 * k2 + 1) * FH + col0];
        #pragma unroll
        for (int r = 0; r < 4; r++) {
            float2 xp = *(const float2*)&xs[(rbase + r) * SXG + 2 * k2];
            ull xd0 = pack2(xp.x, xp.x);
            ull xd1 = pack2(xp.y, xp.y);
            ffma2(acc[r][0], xd0, w0.x);
            ffma2(acc[r][1], xd0, w0.y);
            ffma2(acc[r][0], xd1, w1.x);
            ffma2(acc[r][1], xd1, w1.y);
        }
    }

    #pragma unroll
    for (int r = 0; r < 4; r++) {
        int gr = row0 + rbase + r;
        if (gr < NN) {
            float di = g_dinv[gr];
            float2 a = unpack2(acc[r][0]), b = unpack2(acc[r][1]);
            *(float4*)&g_h[(size_t)gr * FH + col0] =
                make_float4(di * a.x, di * a.y, di * b.x, di * b.y);
        }
    }
}

// ---------------- fused CSR aggregate + x1 + cluster pool ------------------
__global__ void __launch_bounds__(256) node_agg_kernel(const int* __restrict__ cluster,
                                                       const float* __restrict__ b1) {
    int n = (blockIdx.x * 256 + threadIdx.x) >> 5;
    int lane = threadIdx.x & 31;
    if (n >= NN) return;
    int beg = g_ptr[n], dg = g_degi[n];
    int end = beg + dg;
    float2 acc = make_float2(0.f, 0.f);
    int j = beg;
    for (; j + 4 <= end; j += 4) {
        int s0 = g_csrc[j], s1 = g_csrc[j + 1], s2 = g_csrc[j + 2], s3 = g_csrc[j + 3];
        float2 h0 = ((const float2*)g_h)[s0 * 32 + lane];
        float2 h1 = ((const float2*)g_h)[s1 * 32 + lane];
        float2 h2 = ((const float2*)g_h)[s2 * 32 + lane];
        float2 h3 = ((const float2*)g_h)[s3 * 32 + lane];
        acc.x += (h0.x + h1.x) + (h2.x + h3.x);
        acc.y += (h0.y + h1.y) + (h2.y + h3.y);
    }
    for (; j < end; j++) {
        int s = g_csrc[j];
        float2 hv = ((const float2*)g_h)[s * 32 + lane];
        acc.x += hv.x; acc.y += hv.y;
    }
    float2 hn = ((const float2*)g_h)[n * 32 + lane];
    float di = g_dinv[n];
    float2 b = ((const float2*)b1)[lane];
    float2 v;
    v.x = fmaxf(di * (acc.x + hn.x) + b.x, 0.f);
    v.y = fmaxf(di * (acc.y + hn.y) + b.y, 0.f);
    ((float2*)g_x1)[n * 32 + lane] = v;
    int c = cluster[n];
    red2(&g_psum[c * FH + lane * 2], v);
    if (lane == 0) atomicAdd(&g_pcnt[c], 1.0f);
}

// deg_p[t] = column sums of A_hat
__global__ void degp_kernel() {
    int t = blockIdx.x * 256 + threadIdx.x;
    int s0 = blockIdx.y * 64;
    float sum = 0.f;
    #pragma unroll 8
    for (int i = 0; i < 64; i++) sum += g_A[(s0 + i) * KC + t];
    atomicAdd(&g_degp[t], sum);
}

// x_p = psum/cnt ; hps = dinv_p[k] * (x_p @ W2)
__global__ void hp_kernel(const float* __restrict__ W2) {
    __shared__ float xp[FH];
    int k = blockIdx.x, f = threadIdx.x;
    float cnt = fmaxf(g_pcnt[k], 1.0f);
    xp[f] = g_psum[k * FH + f] / cnt;
    __syncthreads();
    float acc = 0.f;
    #pragma unroll
    for (int j = 0; j < FH; j++) acc += xp[j] * W2[j * FOUT + f];
    g_hps[k * FH + f] = acc * rsqrtf(g_degp[k]);
}

// x_p2[t,f] = dinv_p[t] * sum_s A_hat[s,t]*hps[s,f] + b2[f]
__global__ void __launch_bounds__(256) xp2_kernel(const float* __restrict__ b2) {
    __shared__ float As[64][8];
    __shared__ float Hs[64][FH];
    int t0 = blockIdx.x * 8;
    int f = threadIdx.x & 63, g = threadIdx.x >> 6;
    float acc[2] = {0.f, 0.f};
    for (int s0 = 0; s0 < KC; s0 += 64) {
        __syncthreads();
        for (int i = threadIdx.x; i < 64 * 8; i += 256) {
            int si = i >> 3, tj = i & 7;
            As[si][tj] = g_A[(s0 + si) * KC + t0 + tj];
        }
        for (int i = threadIdx.x; i < 64 * 64; i += 256)
            Hs[i >> 6][i & 63] = g_hps[(s0 + (i >> 6)) * FH + (i & 63)];
        __syncthreads();
        #pragma unroll 4
        for (int i = 0; i < 64; i++) {
            float hv = Hs[i][f];
            #pragma unroll
            for (int r = 0; r < 2; r++) acc[r] += As[i][g * 2 + r] * hv;
        }
    }
    float bb = b2[f];
    #pragma unroll
    for (int r = 0; r < 2; r++) {
        int t = t0 + g * 2 + r;
        g_xp2[t * FOUT + f] = rsqrtf(g_degp[t]) * acc[r] + bb;
    }
}

// ---------------- final: out = xp2[cluster] + relu(alpha)*(x1@Wskip + bskip) ----
#define SXF 68
__global__ void __launch_bounds__(256, 4) final_kernel(const int* __restrict__ cluster,
                                                       const float* __restrict__ Wskip,
                                                       const float* __restrict__ bskip,
                                                       const float* __restrict__ alpha,
                                                       float* __restrict__ out) {
    extern __shared__ float fsmem[];
    float* Ws = fsmem;
    float* xs = fsmem + FH * FOUT;

    int tid = threadIdx.x;
    int row0 = blockIdx.x * 64;

    for (int i = tid; i < FH * FOUT / 4; i += 256)
        ((float4*)Ws)[i] = ((const float4*)Wskip)[i];
    for (int i = tid; i < 64 * 16; i += 256) {
        int r = i >> 4, q = i & 15;
        int gr = row0 + r;
        float4 v = (gr < NN) ? ((const float4*)g_x1)[(size_t)gr * 16 + q]
                             : make_float4(0.f, 0.f, 0.f, 0.f);
        *(float4*)&xs[r * SXF + q * 4] = v;
    }
    __syncthreads();

    int lane = tid & 31, warp = tid >> 5;
    int half = lane >> 4, cq = lane & 15;
    int rbase = warp * 8 + half * 4;
    int col0 = cq * 4;

    float ral = fmaxf(alpha[0], 0.f);
    float4 bb = *(const float4*)&bskip[col0];

    ull acc[4][2];
    #pragma unroll
    for (int r = 0; r < 4; r++) { acc[r][0] = 0ull; acc[r][1] = 0ull; }

    #pragma unroll 4
    for (int k2 = 0; k2 < FH / 2; k2++) {
        ulonglong2 w0 = *(const ulonglong2*)&Ws[(2 * k2) * FOUT + col0];
        ulonglong2 w1 = *(const ulonglong2*)&Ws[(2 * k2 + 1) * FOUT + col0];
        #pragma unroll
        for (int r = 0; r < 4; r++) {
            float2 xp = *(const float2*)&xs[(rbase + r) * SXF + 2 * k2];
            ull xd0 = pack2(xp.x, xp.x);
            ull xd1 = pack2(xp.y, xp.y);
            ffma2(acc[r][0], xd0, w0.x);
            ffma2(acc[r][1], xd0, w0.y);
            ffma2(acc[r][0], xd1, w1.x);
            ffma2(acc[r][1], xd1, w1.y);
        }
    }

    #pragma unroll
    for (int r = 0; r < 4; r++) {
        int gr = row0 + rbase + r;
        if (gr < NN) {
            int cl = cluster[gr];
            float4 up = *(const float4*)&g_xp2[cl * FOUT + col0];
            float2 a = unpack2(acc[r][0]), b = unpack2(acc[r][1]);
            float4 o = make_float4(up.x + ral * (a.x + bb.x),
                                   up.y + ral * (a.y + bb.y),
                                   up.z + ral * (b.x + bb.z),
                                   up.w + ral * (b.y + bb.w));
            *(float4*)&out[(size_t)gr * FOUT + col0] = o;
        }
    }
}

// ---------------- launch ----------------
extern "C" void kernel_launch(void* const* d_in, const int* in_sizes, int n_in,
                              void* d_out, int out_size) {
    const float* x       = (const float*)d_in[0];
    const int*   ei      = (const int*)d_in[1];
    const int*   src     = ei;
    const int*   dst     = ei + NE;
    const int*   cluster = (const int*)d_in[2];
    const float* W1      = (const float*)d_in[3];
    const float* b1      = (const float*)d_in[4];
    const float* W2      = (const float*)d_in[5];
    const float* b2      = (const float*)d_in[6];
    const float* Wsk     = (const float*)d_in[7];
    const float* bsk     = (const float*)d_in[8];
    const float* alpha   = (const float*)d_in[9];
    float* out = (float*)d_out;

    const int SMEM1 = (FIN * FH + 64 * SXG) * 4;   // 66560 B
    const int SMEM2 = (FH * FOUT + 64 * SXF) * 4;  // 33792 B
    cudaFuncSetAttribute(gemm1_kernel, cudaFuncAttributeMaxDynamicSharedMemorySize, SMEM1);
    cudaFuncSetAttribute(final_kernel, cudaFuncAttributeMaxDynamicSharedMemorySize, SMEM2);

    const int NBN = (NN + 255) / 256;   // 196

    zero_all_kernel<<<(KC * KC / 4 + 255) / 256, 256>>>();
    edge_pre_kernel<<<(NE + 255) / 256, 256>>>(src, dst, cluster);
    ptr_kernel<<<NBN, 256>>>();
    gemm1_kernel<<<(NN + 63) / 64, 256, SMEM1>>>(x, W1);
    scatter_kernel<<<(NE + 255) / 256, 256>>>(src, dst);
    node_agg_kernel<<<(NN * 32 + 255) / 256, 256>>>(cluster, b1);
    degp_kernel<<<dim3(4, 16), 256>>>();
    hp_kernel<<<KC, 64>>>(W2);
    xp2_kernel<<<KC / 8, 256>>>(b2);
    final_kernel<<<(NN + 63) / 64, 256, SMEM2>>>(cluster, Wsk, bsk, alpha, out);
}

// round 16
// speedup vs baseline: 1.7515x; 1.0124x over previous
#include <cuda_runtime.h>
#include <cuda_bf16.h>

#define NN   50000
#define NE   800000
#define FIN  128
#define FH   64
#define FOUT 64
#define KC   1024

typedef unsigned long long ull;

// ---------------- scratch (device globals; no allocation) ----------------
__device__ __align__(16) float g_h[NN * FH];      // h' = dinv * (x @ W1)
__device__ __align__(16) float g_x1[NN * FH];     // relu(gcn1)
__device__ __align__(16) int   g_degi[NN];        // in-degree (int)
__device__ float g_dinv[NN];
__device__ __align__(16) int   g_ptr[NN];         // CSR row starts
__device__ __align__(16) int   g_cursor[NN];      // scatter cursors
__device__ __align__(16) int   g_csrc[NE];        // CSR src indices (by dst)
__device__ int g_total;                           // CSR bump allocator
__device__ __align__(16) float g_psum[KC * FH];   // cluster sums
__device__ __align__(16) float g_pcnt[KC];
__device__ __align__(16) float g_A[KC * KC];      // pooled adjacency (0/1)
__device__ __align__(16) float g_degp[KC];
__device__ __align__(16) float g_hps[KC * FH];    // dinv_p[s] * (x_p @ W2)
__device__ __align__(16) float g_xp2[KC * FOUT];  // pooled conv output

// ---------------- helpers ----------------
__device__ __forceinline__ ull pack2(float x, float y) {
    ull r;
    asm("mov.b64 %0, {%1, %2};" : "=l"(r) : "f"(x), "f"(y));
    return r;
}
__device__ __forceinline__ float2 unpack2(ull v) {
    float2 f;
    asm("mov.b64 {%0, %1}, %2;" : "=f"(f.x), "=f"(f.y) : "l"(v));
    return f;
}
__device__ __forceinline__ void ffma2(ull& d, ull a, ull b) {
    asm("fma.rn.f32x2 %0, %1, %2, %0;" : "+l"(d) : "l"(a), "l"(b));
}
__device__ __forceinline__ void red2(float* p, float2 v) {
    asm volatile("red.global.add.v2.f32 [%0], {%1,%2};"
                 :: "l"(p), "f"(v.x), "f"(v.y) : "memory");
}

// ---------------- setup kernels ----------------
__global__ void zero_all_kernel() {
    int i = blockIdx.x * blockDim.x + threadIdx.x;
    float4 z = make_float4(0.f, 0.f, 0.f, 0.f);
    if (i < KC * KC / 4) ((float4*)g_A)[i] = z;
    if (i < KC * FH / 4) ((float4*)g_psum)[i] = z;
    if (i < NN / 4)      ((int4*)g_degi)[i] = make_int4(0, 0, 0, 0);
    if (i < KC / 4)      ((float4*)g_pcnt)[i] = z;
    if (i == 0) g_total = 0;
}

// degree counts + pooled adjacency stores (one edge-list pass)
__global__ void edge_pre_kernel(const int* __restrict__ src, const int* __restrict__ dst,
                                const int* __restrict__ cluster) {
    int e = blockIdx.x * blockDim.x + threadIdx.x;
    if (e < NE) {
        int s = src[e], d = dst[e];
        atomicAdd(&g_degi[d], 1);
        g_A[cluster[s] * KC + cluster[d]] = 1.0f;   // idempotent race
    }
}

// CSR offsets: block scan + atomic bump allocator for the block base.
__global__ void ptr_kernel() {
    __shared__ int wsum[8];
    __shared__ int wpre[8];
    __shared__ int sbase;
    int i = blockIdx.x * 256 + threadIdx.x;
    int lane = threadIdx.x & 31, w = threadIdx.x >> 5;
    int v = (i < NN) ? g_degi[i] : 0;
    int x = v;
    #pragma unroll
    for (int d = 1; d < 32; d <<= 1) {
        int y = __shfl_up_sync(0xffffffffu, x, d);
        if (lane >= d) x += y;
    }
    if (lane == 31) wsum[w] = x;
    __syncthreads();
    if (threadIdx.x == 0) {
        int s = 0;
        #pragma unroll
        for (int j = 0; j < 8; j++) { wpre[j] = s; s += wsum[j]; }
        sbase = atomicAdd(&g_total, s);
    }
    __syncthreads();
    int excl = sbase + wpre[w] + x - v;
    if (i < NN) {
        g_ptr[i] = excl;
        g_cursor[i] = excl;
        g_dinv[i] = rsqrtf((float)v + 1.0f);
    }
    if (i < KC) g_A[i * KC + i] = 1.0f;   // A*(1-I)+I => diag exactly 1
}

// bucket edges by dst
__global__ void scatter_kernel(const int* __restrict__ src, const int* __restrict__ dst) {
    int e = blockIdx.x * blockDim.x + threadIdx.x;
    if (e < NE) {
        int pos = atomicAdd(&g_cursor[dst[e]], 1);
        g_csrc[pos] = src[e];
    }
}

// ---------------- gemm1: h' = dinv * (x @ W1) ------------------------------
// R5 compute geometry; W read straight from global (32KB, L1-resident, 16
// distinct addrs/warp/row) instead of smem -> smem 33.8KB, regs<=64 -> 4 CTAs.
#define SXG 132
__global__ void __launch_bounds__(256, 4) gemm1_kernel(const float* __restrict__ x,
                                                       const float* __restrict__ W1) {
    __shared__ float xs[64 * SXG];    // 33792 B

    int tid = threadIdx.x;
    int row0 = blockIdx.x * 64;

    for (int i = tid; i < 64 * 32; i += 256) {
        int r = i >> 5, q = i & 31;
        int gr = row0 + r;
        float4 v = (gr < NN) ? ((const float4*)x)[(size_t)gr * 32 + q]
                             : make_float4(0.f, 0.f, 0.f, 0.f);
        *(float4*)&xs[r * SXG + q * 4] = v;
    }
    __syncthreads();

    int lane = tid & 31, warp = tid >> 5;
    int half = lane >> 4, cq = lane & 15;
    int rbase = warp * 8 + half * 4;
    int col0 = cq * 4;

    ull acc[4][2];
    #pragma unroll
    for (int r = 0; r < 4; r++) { acc[r][0] = 0ull; acc[r][1] = 0ull; }

    #pragma unroll 4
    for (int k2 = 0; k2 < FIN / 2; k2++) {
        ulonglong2 w0 = *(const ulonglong2*)&W1[(2 * k2) * FH + col0];
        ulonglong2 w1 = *(const ulonglong2*)&W1[(2 * k2 + 1) * FH + col0];
        #pragma unroll
        for (int r = 0; r < 4; r++) {
            float2 xp = *(const float2*)&xs[(rbase + r) * SXG + 2 * k2];
            ull xd0 = pack2(xp.x, xp.x);
            ull xd1 = pack2(xp.y, xp.y);
            ffma2(acc[r][0], xd0, w0.x);
            ffma2(acc[r][1], xd0, w0.y);
            ffma2(acc[r][0], xd1, w1.x);
            ffma2(acc[r][1], xd1, w1.y);
        }
    }

    #pragma unroll
    for (int r = 0; r < 4; r++) {
        int gr = row0 + rbase + r;
        if (gr < NN) {
            float di = g_dinv[gr];
            float2 a = unpack2(acc[r][0]), b = unpack2(acc[r][1]);
            *(float4*)&g_h[(size_t)gr * FH + col0] =
                make_float4(di * a.x, di * a.y, di * b.x, di * b.y);
        }
    }
}

// ---------------- fused CSR aggregate + x1 + cluster pool ------------------
__global__ void __launch_bounds__(256) node_agg_kernel(const int* __restrict__ cluster,
                                                       const float* __restrict__ b1) {
    int n = (blockIdx.x * 256 + threadIdx.x) >> 5;
    int lane = threadIdx.x & 31;
    if (n >= NN) return;
    int beg = g_ptr[n], dg = g_degi[n];
    int end = beg + dg;
    float2 acc = make_float2(0.f, 0.f);
    int j = beg;
    for (; j + 4 <= end; j += 4) {
        int s0 = g_csrc[j], s1 = g_csrc[j + 1], s2 = g_csrc[j + 2], s3 = g_csrc[j + 3];
        float2 h0 = ((const float2*)g_h)[s0 * 32 + lane];
        float2 h1 = ((const float2*)g_h)[s1 * 32 + lane];
        float2 h2 = ((const float2*)g_h)[s2 * 32 + lane];
        float2 h3 = ((const float2*)g_h)[s3 * 32 + lane];
        acc.x += (h0.x + h1.x) + (h2.x + h3.x);
        acc.y += (h0.y + h1.y) + (h2.y + h3.y);
    }
    for (; j < end; j++) {
        int s = g_csrc[j];
        float2 hv = ((const float2*)g_h)[s * 32 + lane];
        acc.x += hv.x; acc.y += hv.y;
    }
    float2 hn = ((const float2*)g_h)[n * 32 + lane];
    float di = g_dinv[n];
    float2 b = ((const float2*)b1)[lane];
    float2 v;
    v.x = fmaxf(di * (acc.x + hn.x) + b.x, 0.f);
    v.y = fmaxf(di * (acc.y + hn.y) + b.y, 0.f);
    ((float2*)g_x1)[n * 32 + lane] = v;
    int c = cluster[n];
    red2(&g_psum[c * FH + lane * 2], v);
    if (lane == 0) atomicAdd(&g_pcnt[c], 1.0f);
}

// x_p = psum/cnt ; deg_p[k] = column-sum of A_hat ; hps = dinv_p*(x_p @ W2)
__global__ void hp_kernel(const float* __restrict__ W2) {
    __shared__ float xp[FH];
    __shared__ float dsum[64];
    __shared__ float sdeg;
    int k = blockIdx.x, f = threadIdx.x;   // 64 threads
    float ds = 0.f;
    #pragma unroll
    for (int j = 0; j < 16; j++) ds += g_A[(j * 64 + f) * KC + k];
    dsum[f] = ds;
    float cnt = fmaxf(g_pcnt[k], 1.0f);
    xp[f] = g_psum[k * FH + f] / cnt;
    __syncthreads();
    if (f < 32) {
        float v = dsum[f] + dsum[f + 32];
        #pragma unroll
        for (int o = 16; o > 0; o >>= 1) v += __shfl_down_sync(0xffffffffu, v, o);
        if (f == 0) { sdeg = v; g_degp[k] = v; }
    }
    __syncthreads();
    float acc = 0.f;
    #pragma unroll
    for (int j = 0; j < FH; j++) acc += xp[j] * W2[j * FOUT + f];
    g_hps[k * FH + f] = acc * rsqrtf(sdeg);
}

// x_p2[t,f] = dinv_p[t] * sum_s A_hat[s,t]*hps[s,f] + b2[f]
__global__ void __launch_bounds__(256) xp2_kernel(const float* __restrict__ b2) {
    __shared__ float As[64][8];
    __shared__ float Hs[64][FH];
    int t0 = blockIdx.x * 8;
    int f = threadIdx.x & 63, g = threadIdx.x >> 6;
    float acc[2] = {0.f, 0.f};
    for (int s0 = 0; s0 < KC; s0 += 64) {
        __syncthreads();
        for (int i = threadIdx.x; i < 64 * 8; i += 256) {
            int si = i >> 3, tj = i & 7;
            As[si][tj] = g_A[(s0 + si) * KC + t0 + tj];
        }
        for (int i = threadIdx.x; i < 64 * 64; i += 256)
            Hs[i >> 6][i & 63] = g_hps[(s0 + (i >> 6)) * FH + (i & 63)];
        __syncthreads();
        #pragma unroll 4
        for (int i = 0; i < 64; i++) {
            float hv = Hs[i][f];
            #pragma unroll
            for (int r = 0; r < 2; r++) acc[r] += As[i][g * 2 + r] * hv;
        }
    }
    float bb = b2[f];
    #pragma unroll
    for (int r = 0; r < 2; r++) {
        int t = t0 + g * 2 + r;
        g_xp2[t * FOUT + f] = rsqrtf(g_degp[t]) * acc[r] + bb;
    }
}

// ---------------- final: out = xp2[cluster] + relu(alpha)*(x1@Wskip + bskip) ----
#define SXF 68
__global__ void __launch_bounds__(256, 4) final_kernel(const int* __restrict__ cluster,
                                                       const float* __restrict__ Wskip,
                                                       const float* __restrict__ bskip,
                                                       const float* __restrict__ alpha,
                                                       float* __restrict__ out) {
    extern __shared__ float fsmem[];
    float* Ws = fsmem;
    float* xs = fsmem + FH * FOUT;

    int tid = threadIdx.x;
    int row0 = blockIdx.x * 64;

    for (int i = tid; i < FH * FOUT / 4; i += 256)
        ((float4*)Ws)[i] = ((const float4*)Wskip)[i];
    for (int i = tid; i < 64 * 16; i += 256) {
        int r = i >> 4, q = i & 15;
        int gr = row0 + r;
        float4 v = (gr < NN) ? ((const float4*)g_x1)[(size_t)gr * 16 + q]
                             : make_float4(0.f, 0.f, 0.f, 0.f);
        *(float4*)&xs[r * SXF + q * 4] = v;
    }
    __syncthreads();

    int lane = tid & 31, warp = tid >> 5;
    int half = lane >> 4, cq = lane & 15;
    int rbase = warp * 8 + half * 4;
    int col0 = cq * 4;

    float ral = fmaxf(alpha[0], 0.f);
    float4 bb = *(const float4*)&bskip[col0];

    ull acc[4][2];
    #pragma unroll
    for (int r = 0; r < 4; r++) { acc[r][0] = 0ull; acc[r][1] = 0ull; }

    #pragma unroll 4
    for (int k2 = 0; k2 < FH / 2; k2++) {
        ulonglong2 w0 = *(const ulonglong2*)&Ws[(2 * k2) * FOUT + col0];
        ulonglong2 w1 = *(const ulonglong2*)&Ws[(2 * k2 + 1) * FOUT + col0];
        #pragma unroll
        for (int r = 0; r < 4; r++) {
            float2 xp = *(const float2*)&xs[(rbase + r) * SXF + 2 * k2];
            ull xd0 = pack2(xp.x, xp.x);
            ull xd1 = pack2(xp.y, xp.y);
            ffma2(acc[r][0], xd0, w0.x);
            ffma2(acc[r][1], xd0, w0.y);
            ffma2(acc[r][0], xd1, w1.x);
            ffma2(acc[r][1], xd1, w1.y);
        }
    }

    #pragma unroll
    for (int r = 0; r < 4; r++) {
        int gr = row0 + rbase + r;
        if (gr < NN) {
            int cl = cluster[gr];
            float4 up = *(const float4*)&g_xp2[cl * FOUT + col0];
            float2 a = unpack2(acc[r][0]), b = unpack2(acc[r][1]);
            float4 o = make_float4(up.x + ral * (a.x + bb.x),
                                   up.y + ral * (a.y + bb.y),
                                   up.z + ral * (b.x + bb.z),
                                   up.w + ral * (b.y + bb.w));
            *(float4*)&out[(size_t)gr * FOUT + col0] = o;
        }
    }
}

// ---------------- launch ----------------
extern "C" void kernel_launch(void* const* d_in, const int* in_sizes, int n_in,
                              void* d_out, int out_size) {
    const float* x       = (const float*)d_in[0];
    const int*   ei      = (const int*)d_in[1];
    const int*   src     = ei;
    const int*   dst     = ei + NE;
    const int*   cluster = (const int*)d_in[2];
    const float* W1      = (const float*)d_in[3];
    const float* b1      = (const float*)d_in[4];
    const float* W2      = (const float*)d_in[5];
    const float* b2      = (const float*)d_in[6];
    const float* Wsk     = (const float*)d_in[7];
    const float* bsk     = (const float*)d_in[8];
    const float* alpha   = (const float*)d_in[9];
    float* out = (float*)d_out;

    const int SMEM2 = (FH * FOUT + 64 * SXF) * 4;  // 33792 B
    cudaFuncSetAttribute(final_kernel, cudaFuncAttributeMaxDynamicSharedMemorySize, SMEM2);

    const int NBN = (NN + 255) / 256;   // 196

    zero_all_kernel<<<(KC * KC / 4 + 255) / 256, 256>>>();
    edge_pre_kernel<<<(NE + 255) / 256, 256>>>(src, dst, cluster);
    ptr_kernel<<<NBN, 256>>>();
    gemm1_kernel<<<(NN + 63) / 64, 256>>>(x, W1);
    scatter_kernel<<<(NE + 255) / 256, 256>>>(src, dst);
    node_agg_kernel<<<(NN * 32 + 255) / 256, 256>>>(cluster, b1);
    hp_kernel<<<KC, 64>>>(W2);
    xp2_kernel<<<KC / 8, 256>>>(b2);
    final_kernel<<<(NN + 63) / 64, 256, SMEM2>>>(cluster, Wsk, bsk, alpha, out);
}